// round 1
// baseline (speedup 1.0000x reference)
#include <cuda_runtime.h>

// Problem constants
#define NB 4
#define TT 1500
#define EE 1280
#define NH 20
#define DH 64
#define MR (NB*TT)          // 6000 rows
#define QKSCALE 0.125f      // 64^-0.5

// Scratch (static device globals: allocation-free per harness rules)
static __device__ float g_q[(size_t)NB*NH*TT*DH];    // [b,h,t,d]
static __device__ float g_k[(size_t)NB*NH*TT*DH];
static __device__ float g_v[(size_t)NB*NH*TT*DH];
static __device__ float g_ctx[(size_t)MR*EE];        // [b*T+t, h*64+d]

// ---- packed f32x2 helpers (2x fp32 FMA throughput on sm_103a) ----
__device__ __forceinline__ unsigned long long dup2(float a){
    unsigned long long r;
    asm("mov.b64 %0, {%1, %1};" : "=l"(r) : "f"(a));
    return r;
}
__device__ __forceinline__ void fma2(unsigned long long &d, unsigned long long a, unsigned long long b){
    asm("fma.rn.f32x2 %0, %1, %2, %0;" : "+l"(d) : "l"(a), "l"(b));
}
__device__ __forceinline__ float2 un2(unsigned long long v){
    float2 r;
    asm("mov.b64 {%0, %1}, %2;" : "=f"(r.x), "=f"(r.y) : "l"(v));
    return r;
}

// ============================================================================
// Fused QKV GEMM: C[6000, 3840] = X[6000,1280] @ [Wq|Wk|Wv]^T (+bias, +scale)
// Epilogue scatters into g_q/g_k/g_v in [b,h,t,d] layout.
// Tile: 128x128x8, 256 threads, 8x8 per thread, f32x2 accumulators.
// ============================================================================
__global__ __launch_bounds__(256) void qkv_gemm(
    const float* __restrict__ X,
    const float* __restrict__ Wq, const float* __restrict__ bq,
    const float* __restrict__ Wk,
    const float* __restrict__ Wv, const float* __restrict__ bv)
{
    __shared__ float As[8][128];
    __shared__ float Bs[8][128];
    const int tid  = threadIdx.x;
    const int row0 = blockIdx.y * 128;
    const int col0 = blockIdx.x * 128;
    const int which = col0 / EE;               // 0=q, 1=k, 2=v (1280 % 128 == 0)
    const float* W = (which == 0) ? Wq : (which == 1 ? Wk : Wv);
    const int wcol0 = col0 - which * EE;

    const int lrow = tid >> 1;                 // 0..127
    const int lseg = (tid & 1) * 4;            // 0 or 4
    const bool aval = (row0 + lrow) < MR;
    const float* aptr = X + (size_t)(row0 + lrow) * EE + lseg;
    const float* bptr = W + (size_t)(wcol0 + lrow) * EE + lseg;

    const int tx = tid & 15;
    const int ty = tid >> 4;

    unsigned long long acc[8][4];
    #pragma unroll
    for (int i = 0; i < 8; i++)
        #pragma unroll
        for (int p = 0; p < 4; p++) acc[i][p] = 0ULL;

    for (int k0 = 0; k0 < EE; k0 += 8) {
        float4 av  = aval ? *(const float4*)(aptr + k0) : make_float4(0.f,0.f,0.f,0.f);
        float4 bv4 = *(const float4*)(bptr + k0);
        __syncthreads();
        As[lseg+0][lrow] = av.x;  As[lseg+1][lrow] = av.y;
        As[lseg+2][lrow] = av.z;  As[lseg+3][lrow] = av.w;
        Bs[lseg+0][lrow] = bv4.x; Bs[lseg+1][lrow] = bv4.y;
        Bs[lseg+2][lrow] = bv4.z; Bs[lseg+3][lrow] = bv4.w;
        __syncthreads();
        #pragma unroll
        for (int kk = 0; kk < 8; kk++) {
            float4 a0 = *(const float4*)&As[kk][ty*8];
            float4 a1 = *(const float4*)&As[kk][ty*8+4];
            const unsigned long long* bp = (const unsigned long long*)&Bs[kk][tx*8];
            unsigned long long b0 = bp[0], b1 = bp[1], b2 = bp[2], b3 = bp[3];
            float a[8] = {a0.x,a0.y,a0.z,a0.w,a1.x,a1.y,a1.z,a1.w};
            #pragma unroll
            for (int i = 0; i < 8; i++) {
                unsigned long long ad = dup2(a[i]);
                fma2(acc[i][0], ad, b0);
                fma2(acc[i][1], ad, b1);
                fma2(acc[i][2], ad, b2);
                fma2(acc[i][3], ad, b3);
            }
        }
    }

    // Epilogue: bias (+scale for q), scatter to [b,h,t,d]
    const int cbase = wcol0 + tx * 8;     // column within the 1280-wide matrix
    const int hh = cbase >> 6;
    const int d0 = cbase & 63;
    float bias[8];
    #pragma unroll
    for (int j = 0; j < 8; j++) bias[j] = 0.f;
    if (which == 0) {
        float4 t0 = *(const float4*)&bq[cbase];
        float4 t1 = *(const float4*)&bq[cbase+4];
        bias[0]=t0.x; bias[1]=t0.y; bias[2]=t0.z; bias[3]=t0.w;
        bias[4]=t1.x; bias[5]=t1.y; bias[6]=t1.z; bias[7]=t1.w;
    } else if (which == 2) {
        float4 t0 = *(const float4*)&bv[cbase];
        float4 t1 = *(const float4*)&bv[cbase+4];
        bias[0]=t0.x; bias[1]=t0.y; bias[2]=t0.z; bias[3]=t0.w;
        bias[4]=t1.x; bias[5]=t1.y; bias[6]=t1.z; bias[7]=t1.w;
    }
    float* dstBase = (which == 0) ? g_q : (which == 1 ? g_k : g_v);

    #pragma unroll
    for (int i = 0; i < 8; i++) {
        int r = row0 + ty * 8 + i;
        if (r >= MR) continue;
        int b_ = r / TT;
        int t_ = r - b_ * TT;
        float c[8];
        #pragma unroll
        for (int p = 0; p < 4; p++) { float2 f = un2(acc[i][p]); c[2*p] = f.x; c[2*p+1] = f.y; }
        #pragma unroll
        for (int j = 0; j < 8; j++) {
            float v = c[j] + bias[j];
            if (which == 0) v *= QKSCALE;
            c[j] = v;
        }
        float* dst = dstBase + ((size_t)(b_ * NH + hh) * TT + t_) * DH + d0;
        *(float4*)dst       = make_float4(c[0],c[1],c[2],c[3]);
        *(float4*)(dst + 4) = make_float4(c[4],c[5],c[6],c[7]);
    }
}

// ============================================================================
// Flash attention, fp32. Grid (24 q-tiles, 80 heads), 256 threads.
// 64x64 tiles, K transposed in smem (conflict-free LDS.128), online softmax.
// Writes g_ctx in [b*T+t, h*64+d] layout for the output projection.
// ============================================================================
__global__ __launch_bounds__(256) void attn_kernel()
{
    __shared__ float Qs[64*64];
    __shared__ float KtPs[64*64];   // K^T during S-compute, then reused for P
    __shared__ float Vs[64*64];

    const int tid = threadIdx.x;
    const int tx = tid & 15;
    const int ty = tid >> 4;
    const int bh = blockIdx.y;              // b*NH + h
    const int b_ = bh / NH;
    const int h_ = bh - b_ * NH;
    const float* qb = g_q + (size_t)bh * TT * DH;
    const float* kb = g_k + (size_t)bh * TT * DH;
    const float* vb = g_v + (size_t)bh * TT * DH;
    const int q0 = blockIdx.x * 64;

    // Load Q tile (zero-pad invalid rows)
    #pragma unroll
    for (int i = 0; i < 4; i++) {
        int f = tid + 256 * i;
        int row = f >> 4;
        int c4 = (f & 15) * 4;
        float4 qv = make_float4(0.f,0.f,0.f,0.f);
        if (q0 + row < TT) qv = *(const float4*)(qb + (size_t)(q0 + row) * DH + c4);
        *(float4*)&Qs[row * 64 + c4] = qv;
    }

    float m_i[4], l_i[4], o[4][4];
    #pragma unroll
    for (int i = 0; i < 4; i++) {
        m_i[i] = -1e30f; l_i[i] = 0.f;
        #pragma unroll
        for (int j = 0; j < 4; j++) o[i][j] = 0.f;
    }

    for (int kt = 0; kt < 24; kt++) {
        const int k0 = kt * 64;
        __syncthreads();   // previous tile's P/V reads done (also orders Q store)

        // Load K transposed + V
        {
            int kcol = tid & 63;
            int d0 = (tid >> 6) * 16;
            bool kvalid = (k0 + kcol) < TT;
            #pragma unroll
            for (int i = 0; i < 4; i++) {
                float4 kv = make_float4(0.f,0.f,0.f,0.f);
                if (kvalid) kv = *(const float4*)(kb + (size_t)(k0 + kcol) * DH + d0 + 4*i);
                KtPs[(d0 + 4*i + 0) * 64 + kcol] = kv.x;
                KtPs[(d0 + 4*i + 1) * 64 + kcol] = kv.y;
                KtPs[(d0 + 4*i + 2) * 64 + kcol] = kv.z;
                KtPs[(d0 + 4*i + 3) * 64 + kcol] = kv.w;
            }
            #pragma unroll
            for (int i = 0; i < 4; i++) {
                int f = tid + 256 * i;
                int row = f >> 4;
                int c4 = (f & 15) * 4;
                float4 vv = make_float4(0.f,0.f,0.f,0.f);
                if (k0 + row < TT) vv = *(const float4*)(vb + (size_t)(k0 + row) * DH + c4);
                *(float4*)&Vs[row * 64 + c4] = vv;
            }
        }
        __syncthreads();

        // S = Q K^T  (4x4 per thread)
        float s[4][4];
        #pragma unroll
        for (int i = 0; i < 4; i++)
            #pragma unroll
            for (int j = 0; j < 4; j++) s[i][j] = 0.f;

        #pragma unroll 4
        for (int d = 0; d < 64; d++) {
            float4 kv = *(const float4*)&KtPs[d * 64 + tx * 4];
            #pragma unroll
            for (int i = 0; i < 4; i++) {
                float qv = Qs[(ty*4 + i) * 64 + d];
                s[i][0] += qv * kv.x;
                s[i][1] += qv * kv.y;
                s[i][2] += qv * kv.z;
                s[i][3] += qv * kv.w;
            }
        }
        // Mask invalid key columns
        #pragma unroll
        for (int j = 0; j < 4; j++) {
            if (k0 + tx*4 + j >= TT) {
                #pragma unroll
                for (int i = 0; i < 4; i++) s[i][j] = -1e30f;
            }
        }

        // Online softmax (row groups of 16 lanes)
        #pragma unroll
        for (int i = 0; i < 4; i++) {
            float rm = fmaxf(fmaxf(s[i][0], s[i][1]), fmaxf(s[i][2], s[i][3]));
            rm = fmaxf(rm, __shfl_xor_sync(0xffffffffu, rm, 1));
            rm = fmaxf(rm, __shfl_xor_sync(0xffffffffu, rm, 2));
            rm = fmaxf(rm, __shfl_xor_sync(0xffffffffu, rm, 4));
            rm = fmaxf(rm, __shfl_xor_sync(0xffffffffu, rm, 8));
            float mn = fmaxf(m_i[i], rm);
            float alpha = __expf(m_i[i] - mn);
            float rs = 0.f;
            #pragma unroll
            for (int j = 0; j < 4; j++) { s[i][j] = __expf(s[i][j] - mn); rs += s[i][j]; }
            rs += __shfl_xor_sync(0xffffffffu, rs, 1);
            rs += __shfl_xor_sync(0xffffffffu, rs, 2);
            rs += __shfl_xor_sync(0xffffffffu, rs, 4);
            rs += __shfl_xor_sync(0xffffffffu, rs, 8);
            l_i[i] = l_i[i] * alpha + rs;
            m_i[i] = mn;
            #pragma unroll
            for (int j = 0; j < 4; j++) o[i][j] *= alpha;
        }

        __syncthreads();   // all done reading K^T
        // Write P into the Kt buffer
        #pragma unroll
        for (int i = 0; i < 4; i++)
            *(float4*)&KtPs[(ty*4 + i) * 64 + tx*4] = make_float4(s[i][0], s[i][1], s[i][2], s[i][3]);
        __syncthreads();

        // O += P V
        #pragma unroll 4
        for (int kk = 0; kk < 64; kk++) {
            float4 vv = *(const float4*)&Vs[kk * 64 + tx * 4];
            #pragma unroll
            for (int i = 0; i < 4; i++) {
                float pv = KtPs[(ty*4 + i) * 64 + kk];
                o[i][0] += pv * vv.x;
                o[i][1] += pv * vv.y;
                o[i][2] += pv * vv.z;
                o[i][3] += pv * vv.w;
            }
        }
    }

    // Epilogue: normalize, write ctx [b*T+t, h*64+d]
    #pragma unroll
    for (int i = 0; i < 4; i++) {
        int row = q0 + ty*4 + i;
        if (row >= TT) continue;
        float inv = 1.0f / l_i[i];
        float* dst = g_ctx + ((size_t)(b_ * TT + row)) * EE + h_ * DH + tx * 4;
        *(float4*)dst = make_float4(o[i][0]*inv, o[i][1]*inv, o[i][2]*inv, o[i][3]*inv);
    }
}

// ============================================================================
// Output projection: out[6000,1280] = ctx @ Wo^T + bo
// ============================================================================
__global__ __launch_bounds__(256) void out_gemm(
    const float* __restrict__ Wo, const float* __restrict__ bo,
    float* __restrict__ out)
{
    __shared__ float As[8][128];
    __shared__ float Bs[8][128];
    const int tid  = threadIdx.x;
    const int row0 = blockIdx.y * 128;
    const int col0 = blockIdx.x * 128;

    const int lrow = tid >> 1;
    const int lseg = (tid & 1) * 4;
    const bool aval = (row0 + lrow) < MR;
    const float* aptr = g_ctx + (size_t)(row0 + lrow) * EE + lseg;
    const float* bptr = Wo + (size_t)(col0 + lrow) * EE + lseg;

    const int tx = tid & 15;
    const int ty = tid >> 4;

    unsigned long long acc[8][4];
    #pragma unroll
    for (int i = 0; i < 8; i++)
        #pragma unroll
        for (int p = 0; p < 4; p++) acc[i][p] = 0ULL;

    for (int k0 = 0; k0 < EE; k0 += 8) {
        float4 av  = aval ? *(const float4*)(aptr + k0) : make_float4(0.f,0.f,0.f,0.f);
        float4 bv4 = *(const float4*)(bptr + k0);
        __syncthreads();
        As[lseg+0][lrow] = av.x;  As[lseg+1][lrow] = av.y;
        As[lseg+2][lrow] = av.z;  As[lseg+3][lrow] = av.w;
        Bs[lseg+0][lrow] = bv4.x; Bs[lseg+1][lrow] = bv4.y;
        Bs[lseg+2][lrow] = bv4.z; Bs[lseg+3][lrow] = bv4.w;
        __syncthreads();
        #pragma unroll
        for (int kk = 0; kk < 8; kk++) {
            float4 a0 = *(const float4*)&As[kk][ty*8];
            float4 a1 = *(const float4*)&As[kk][ty*8+4];
            const unsigned long long* bp = (const unsigned long long*)&Bs[kk][tx*8];
            unsigned long long b0 = bp[0], b1 = bp[1], b2 = bp[2], b3 = bp[3];
            float a[8] = {a0.x,a0.y,a0.z,a0.w,a1.x,a1.y,a1.z,a1.w};
            #pragma unroll
            for (int i = 0; i < 8; i++) {
                unsigned long long ad = dup2(a[i]);
                fma2(acc[i][0], ad, b0);
                fma2(acc[i][1], ad, b1);
                fma2(acc[i][2], ad, b2);
                fma2(acc[i][3], ad, b3);
            }
        }
    }

    const int cbase = col0 + tx * 8;
    float4 t0 = *(const float4*)&bo[cbase];
    float4 t1 = *(const float4*)&bo[cbase+4];
    float bias[8] = {t0.x,t0.y,t0.z,t0.w,t1.x,t1.y,t1.z,t1.w};

    #pragma unroll
    for (int i = 0; i < 8; i++) {
        int r = row0 + ty * 8 + i;
        if (r >= MR) continue;
        float c[8];
        #pragma unroll
        for (int p = 0; p < 4; p++) { float2 f = un2(acc[i][p]); c[2*p] = f.x; c[2*p+1] = f.y; }
        #pragma unroll
        for (int j = 0; j < 8; j++) c[j] += bias[j];
        float* dst = out + (size_t)r * EE + cbase;
        *(float4*)dst       = make_float4(c[0],c[1],c[2],c[3]);
        *(float4*)(dst + 4) = make_float4(c[4],c[5],c[6],c[7]);
    }
}

extern "C" void kernel_launch(void* const* d_in, const int* in_sizes, int n_in,
                              void* d_out, int out_size)
{
    const float* X  = (const float*)d_in[0];
    const float* Wq = (const float*)d_in[1];
    const float* bq = (const float*)d_in[2];
    const float* Wk = (const float*)d_in[3];
    const float* Wv = (const float*)d_in[4];
    const float* bv = (const float*)d_in[5];
    const float* Wo = (const float*)d_in[6];
    const float* bo = (const float*)d_in[7];
    float* out = (float*)d_out;

    dim3 g1(3 * EE / 128, (MR + 127) / 128);   // (30, 47)
    qkv_gemm<<<g1, 256>>>(X, Wq, bq, Wk, Wv, bv);

    dim3 g2((TT + 63) / 64, NB * NH);          // (24, 80)
    attn_kernel<<<g2, 256>>>();

    dim3 g3(EE / 128, (MR + 127) / 128);       // (10, 47)
    out_gemm<<<g3, 256>>>(Wo, bo, out);
}

// round 3
// speedup vs baseline: 1.2282x; 1.2282x over previous
#include <cuda_runtime.h>
#include <cuda_bf16.h>
#include <cstdint>

// Problem constants
#define NB 4
#define TT 1500
#define EE 1280
#define NH 20
#define DH 64
#define MR (NB*TT)          // 6000 rows
#define QKSCALE 0.125f

// GEMM tiling: block 128x128, k-chunk 16, 8 warps (2x4), warp tile 64x32
#define BK 16
#define NCH (EE/BK)         // 80 chunks
#define ROWSTRIDE 48        // bytes per smem row (16 bf16 + 8 pad) - conflict-free ldmatrix
#define TILE_SZ (128*ROWSTRIDE)      // 6144 B per bf16 tile
#define STAGE_SZ (4*TILE_SZ)         // Ahi,Alo,Bhi,Blo = 24576 B
#define SMEM_TOTAL (2*STAGE_SZ)      // 49152 B

// Scratch
static __device__ float g_q[(size_t)NB*NH*TT*DH];    // [b,h,t,d]
static __device__ float g_k[(size_t)NB*NH*TT*DH];
static __device__ float g_v[(size_t)NB*NH*TT*DH];
static __device__ float g_ctx[(size_t)MR*EE];        // [b*T+t, h*64+d]

// ---------------- packed f32x2 helpers ----------------
__device__ __forceinline__ unsigned long long dup2(float a){
    unsigned long long r;
    asm("mov.b64 %0, {%1, %1};" : "=l"(r) : "f"(a));
    return r;
}
__device__ __forceinline__ void fma2(unsigned long long &d, unsigned long long a, unsigned long long b){
    asm("fma.rn.f32x2 %0, %1, %2, %0;" : "+l"(d) : "l"(a), "l"(b));
}
__device__ __forceinline__ unsigned long long mul2(unsigned long long a, unsigned long long b){
    unsigned long long r;
    asm("mul.rn.f32x2 %0, %1, %2;" : "=l"(r) : "l"(a), "l"(b));
    return r;
}
__device__ __forceinline__ float2 un2(unsigned long long v){
    float2 r;
    asm("mov.b64 {%0, %1}, %2;" : "=f"(r.x), "=f"(r.y) : "l"(v));
    return r;
}

// ---------------- tensor-core helpers (sm_80-compatible PTX) ----------------
__device__ __forceinline__ uint32_t smem_u32(const void* p){
    uint32_t a;
    asm("{ .reg .u64 t; cvta.to.shared.u64 t, %1; cvt.u32.u64 %0, t; }" : "=r"(a) : "l"(p));
    return a;
}
__device__ __forceinline__ void ldx4(uint32_t* r, uint32_t addr){
    asm volatile("ldmatrix.sync.aligned.m8n8.x4.shared.b16 {%0,%1,%2,%3}, [%4];"
        : "=r"(r[0]), "=r"(r[1]), "=r"(r[2]), "=r"(r[3]) : "r"(addr));
}
__device__ __forceinline__ void ldx2(uint32_t* r, uint32_t addr){
    asm volatile("ldmatrix.sync.aligned.m8n8.x2.shared.b16 {%0,%1}, [%2];"
        : "=r"(r[0]), "=r"(r[1]) : "r"(addr));
}
__device__ __forceinline__ void mma_bf16(float* d, const uint32_t* a, const uint32_t* b){
    asm volatile(
        "mma.sync.aligned.m16n8k16.row.col.f32.bf16.bf16.f32 "
        "{%0,%1,%2,%3}, {%4,%5,%6,%7}, {%8,%9}, {%0,%1,%2,%3};"
        : "+f"(d[0]), "+f"(d[1]), "+f"(d[2]), "+f"(d[3])
        : "r"(a[0]), "r"(a[1]), "r"(a[2]), "r"(a[3]), "r"(b[0]), "r"(b[1]));
}

// Split float4 into bf16 hi (rounded) and lo (residual) packed pairs.
__device__ __forceinline__ void split4(float4 f, uint2& H, uint2& L){
    __nv_bfloat16 hx = __float2bfloat16(f.x);
    __nv_bfloat16 hy = __float2bfloat16(f.y);
    __nv_bfloat16 hz = __float2bfloat16(f.z);
    __nv_bfloat16 hw = __float2bfloat16(f.w);
    float lx = f.x - __bfloat162float(hx);
    float ly = f.y - __bfloat162float(hy);
    float lz = f.z - __bfloat162float(hz);
    float lw = f.w - __bfloat162float(hw);
    union { __nv_bfloat162 h2[2]; uint2 u; } A, B;
    A.h2[0] = __halves2bfloat162(hx, hy);
    A.h2[1] = __halves2bfloat162(hz, hw);
    B.h2[0] = __floats2bfloat162_rn(lx, ly);
    B.h2[1] = __floats2bfloat162_rn(lz, lw);
    H = A.u; L = B.u;
}

// ============================================================================
// Main loop: acc(128x128) += A[row0:+128, :1280] @ B[0:128, :1280]^T
// bf16 split (hh + hl + lh), double-buffered smem, register prefetch.
// acc[mt][nt][4] per-thread fragments (warp 64x32).
// ============================================================================
__device__ __forceinline__ void mm_loop(
    const float* __restrict__ Ab, const float* __restrict__ Bb, int row0,
    char* sm, uint32_t smb, float acc[4][4][4])
{
    const int tid  = threadIdx.x;
    const int lane = tid & 31;
    const int wid  = tid >> 5;
    const int warp_m = wid >> 2;          // 0..1
    const int warp_n = wid & 3;           // 0..3

    const int srow  = tid >> 1;           // 0..127
    const int shalf = (tid & 1) * 8;      // 0 or 8
    const bool aval = (row0 + srow) < MR;
    const float* ap = Ab + (size_t)(row0 + srow) * EE + shalf;
    const float* bp = Bb + (size_t)srow * EE + shalf;

    // ldmatrix base addresses (per thread)
    const uint32_t a_rd = smb + (uint32_t)(warp_m*64 + (lane & 15)) * ROWSTRIDE + (lane >> 4) * 16;
    const uint32_t b_rd = smb + 2*TILE_SZ + (uint32_t)(warp_n*32 + (lane & 7)) * ROWSTRIDE + ((lane >> 3) & 1) * 16;
    // store offsets
    const uint32_t st0 = (uint32_t)srow * ROWSTRIDE + shalf * 2;

    float4 a0, a1, b0, b1;
    a0 = aval ? *(const float4*)(ap)     : make_float4(0.f,0.f,0.f,0.f);
    a1 = aval ? *(const float4*)(ap + 4) : make_float4(0.f,0.f,0.f,0.f);
    b0 = *(const float4*)(bp);
    b1 = *(const float4*)(bp + 4);

    #pragma unroll 1
    for (int i = 0; i < NCH; i++) {
        char* stg = sm + (i & 1) * STAGE_SZ;
        uint2 H, L;
        split4(a0, H, L);
        *(uint2*)(stg + st0)               = H;
        *(uint2*)(stg + TILE_SZ + st0)     = L;
        split4(a1, H, L);
        *(uint2*)(stg + st0 + 8)           = H;
        *(uint2*)(stg + TILE_SZ + st0 + 8) = L;
        split4(b0, H, L);
        *(uint2*)(stg + 2*TILE_SZ + st0)       = H;
        *(uint2*)(stg + 3*TILE_SZ + st0)       = L;
        split4(b1, H, L);
        *(uint2*)(stg + 2*TILE_SZ + st0 + 8)   = H;
        *(uint2*)(stg + 3*TILE_SZ + st0 + 8)   = L;

        if (i + 1 < NCH) {
            const float* apn = ap + (i+1)*BK;
            const float* bpn = bp + (i+1)*BK;
            a0 = aval ? *(const float4*)(apn)     : make_float4(0.f,0.f,0.f,0.f);
            a1 = aval ? *(const float4*)(apn + 4) : make_float4(0.f,0.f,0.f,0.f);
            b0 = *(const float4*)(bpn);
            b1 = *(const float4*)(bpn + 4);
        }
        __syncthreads();

        const uint32_t soff = (uint32_t)(i & 1) * STAGE_SZ;
        uint32_t bh[4][2], bl[4][2];
        #pragma unroll
        for (int nt = 0; nt < 4; nt++) {
            ldx2(bh[nt], b_rd + soff + nt*8*ROWSTRIDE);
            ldx2(bl[nt], b_rd + soff + nt*8*ROWSTRIDE + TILE_SZ);
        }
        #pragma unroll
        for (int mt = 0; mt < 4; mt++) {
            uint32_t ah[4], al[4];
            ldx4(ah, a_rd + soff + mt*16*ROWSTRIDE);
            ldx4(al, a_rd + soff + mt*16*ROWSTRIDE + TILE_SZ);
            #pragma unroll
            for (int nt = 0; nt < 4; nt++) {
                mma_bf16(acc[mt][nt], ah, bh[nt]);
                mma_bf16(acc[mt][nt], ah, bl[nt]);
                mma_bf16(acc[mt][nt], al, bh[nt]);
            }
        }
        __syncthreads();
    }
}

// ============================================================================
// QKV GEMM: grid (30, 47). blockIdx.x: 0-9 q, 10-19 k, 20-29 v.
// ============================================================================
__global__ __launch_bounds__(256, 2) void qkv_mm(
    const float* __restrict__ X,
    const float* __restrict__ Wq, const float* __restrict__ bq,
    const float* __restrict__ Wk,
    const float* __restrict__ Wv, const float* __restrict__ bv)
{
    extern __shared__ char sm[];
    uint32_t smb = smem_u32(sm);
    const int tid = threadIdx.x;
    const int lane = tid & 31;
    const int wid = tid >> 5;
    const int warp_m = wid >> 2, warp_n = wid & 3;

    const int which = blockIdx.x / 10;
    const int wcol0 = (blockIdx.x - which*10) * 128;
    const int row0  = blockIdx.y * 128;
    const float* W = (which == 0) ? Wq : (which == 1 ? Wk : Wv);
    const float* bias = (which == 0) ? bq : (which == 2 ? bv : nullptr);
    const float scl = (which == 0) ? QKSCALE : 1.0f;
    float* dstBase = (which == 0) ? g_q : (which == 1 ? g_k : g_v);

    float acc[4][4][4];
    #pragma unroll
    for (int mt = 0; mt < 4; mt++)
        #pragma unroll
        for (int nt = 0; nt < 4; nt++)
            #pragma unroll
            for (int j = 0; j < 4; j++) acc[mt][nt][j] = 0.f;

    mm_loop(X, W + (size_t)wcol0 * EE, row0, sm, smb, acc);

    const int g = lane >> 2, t4 = lane & 3;
    #pragma unroll
    for (int mt = 0; mt < 4; mt++) {
        #pragma unroll
        for (int nt = 0; nt < 4; nt++) {
            int col = wcol0 + warp_n*32 + nt*8 + 2*t4;
            float2 bb = bias ? *(const float2*)(bias + col) : make_float2(0.f, 0.f);
            int h = col >> 6, d = col & 63;
            int r0w = row0 + warp_m*64 + mt*16 + g;
            if (r0w < MR) {
                int b_ = r0w / TT, t_ = r0w - b_*TT;
                float2 v = make_float2((acc[mt][nt][0] + bb.x)*scl, (acc[mt][nt][1] + bb.y)*scl);
                *(float2*)(dstBase + ((size_t)(b_*NH + h)*TT + t_)*DH + d) = v;
            }
            int r1w = r0w + 8;
            if (r1w < MR) {
                int b_ = r1w / TT, t_ = r1w - b_*TT;
                float2 v = make_float2((acc[mt][nt][2] + bb.x)*scl, (acc[mt][nt][3] + bb.y)*scl);
                *(float2*)(dstBase + ((size_t)(b_*NH + h)*TT + t_)*DH + d) = v;
            }
        }
    }
}

// ============================================================================
// Output projection: out = ctx @ Wo^T + bo. grid (10, 47).
// ============================================================================
__global__ __launch_bounds__(256, 2) void out_mm(
    const float* __restrict__ Wo, const float* __restrict__ bo,
    float* __restrict__ out)
{
    extern __shared__ char sm[];
    uint32_t smb = smem_u32(sm);
    const int tid = threadIdx.x;
    const int lane = tid & 31;
    const int wid = tid >> 5;
    const int warp_m = wid >> 2, warp_n = wid & 3;
    const int col0 = blockIdx.x * 128;
    const int row0 = blockIdx.y * 128;

    float acc[4][4][4];
    #pragma unroll
    for (int mt = 0; mt < 4; mt++)
        #pragma unroll
        for (int nt = 0; nt < 4; nt++)
            #pragma unroll
            for (int j = 0; j < 4; j++) acc[mt][nt][j] = 0.f;

    mm_loop(g_ctx, Wo + (size_t)col0 * EE, row0, sm, smb, acc);

    const int g = lane >> 2, t4 = lane & 3;
    #pragma unroll
    for (int mt = 0; mt < 4; mt++) {
        #pragma unroll
        for (int nt = 0; nt < 4; nt++) {
            int col = col0 + warp_n*32 + nt*8 + 2*t4;
            float2 bb = *(const float2*)(bo + col);
            int r0w = row0 + warp_m*64 + mt*16 + g;
            if (r0w < MR) {
                float2 v = make_float2(acc[mt][nt][0] + bb.x, acc[mt][nt][1] + bb.y);
                *(float2*)(out + (size_t)r0w*EE + col) = v;
            }
            int r1w = r0w + 8;
            if (r1w < MR) {
                float2 v = make_float2(acc[mt][nt][2] + bb.x, acc[mt][nt][3] + bb.y);
                *(float2*)(out + (size_t)r1w*EE + col) = v;
            }
        }
    }
}

// ============================================================================
// Flash attention, fp32 with packed f32x2 inner products.
// Grid (24 q-tiles, 80 heads), 256 threads, 64x64 tiles.
// ============================================================================
__global__ __launch_bounds__(256) void attn_kernel()
{
    __shared__ float Qs[64*64];
    __shared__ float KtPs[64*64];
    __shared__ float Vs[64*64];

    const int tid = threadIdx.x;
    const int tx = tid & 15;
    const int ty = tid >> 4;
    const int bh = blockIdx.y;
    const int b_ = bh / NH;
    const int h_ = bh - b_ * NH;
    const float* qb = g_q + (size_t)bh * TT * DH;
    const float* kb = g_k + (size_t)bh * TT * DH;
    const float* vb = g_v + (size_t)bh * TT * DH;
    const int q0 = blockIdx.x * 64;

    #pragma unroll
    for (int i = 0; i < 4; i++) {
        int f = tid + 256 * i;
        int row = f >> 4;
        int c4 = (f & 15) * 4;
        float4 qv = make_float4(0.f,0.f,0.f,0.f);
        if (q0 + row < TT) qv = *(const float4*)(qb + (size_t)(q0 + row) * DH + c4);
        *(float4*)&Qs[row * 64 + c4] = qv;
    }

    float m_i[4], l_i[4];
    unsigned long long o2[4][2];
    #pragma unroll
    for (int i = 0; i < 4; i++) {
        m_i[i] = -1e30f; l_i[i] = 0.f;
        o2[i][0] = 0ULL; o2[i][1] = 0ULL;
    }

    for (int kt = 0; kt < 24; kt++) {
        const int k0 = kt * 64;
        __syncthreads();

        {
            int kcol = tid & 63;
            int d0 = (tid >> 6) * 16;
            bool kvalid = (k0 + kcol) < TT;
            #pragma unroll
            for (int i = 0; i < 4; i++) {
                float4 kv = make_float4(0.f,0.f,0.f,0.f);
                if (kvalid) kv = *(const float4*)(kb + (size_t)(k0 + kcol) * DH + d0 + 4*i);
                KtPs[(d0 + 4*i + 0) * 64 + kcol] = kv.x;
                KtPs[(d0 + 4*i + 1) * 64 + kcol] = kv.y;
                KtPs[(d0 + 4*i + 2) * 64 + kcol] = kv.z;
                KtPs[(d0 + 4*i + 3) * 64 + kcol] = kv.w;
            }
            #pragma unroll
            for (int i = 0; i < 4; i++) {
                int f = tid + 256 * i;
                int row = f >> 4;
                int c4 = (f & 15) * 4;
                float4 vv = make_float4(0.f,0.f,0.f,0.f);
                if (k0 + row < TT) vv = *(const float4*)(vb + (size_t)(k0 + row) * DH + c4);
                *(float4*)&Vs[row * 64 + c4] = vv;
            }
        }
        __syncthreads();

        unsigned long long s2[4][2];
        #pragma unroll
        for (int i = 0; i < 4; i++) { s2[i][0] = 0ULL; s2[i][1] = 0ULL; }

        #pragma unroll 2
        for (int d = 0; d < 64; d++) {
            const unsigned long long* kp = (const unsigned long long*)(KtPs + d*64 + tx*4);
            unsigned long long k01 = kp[0], k23 = kp[1];
            #pragma unroll
            for (int i = 0; i < 4; i++) {
                unsigned long long qd = dup2(Qs[(ty*4 + i)*64 + d]);
                fma2(s2[i][0], qd, k01);
                fma2(s2[i][1], qd, k23);
            }
        }

        float s[4][4];
        #pragma unroll
        for (int i = 0; i < 4; i++) {
            float2 a = un2(s2[i][0]), b = un2(s2[i][1]);
            s[i][0] = a.x; s[i][1] = a.y; s[i][2] = b.x; s[i][3] = b.y;
        }
        #pragma unroll
        for (int j = 0; j < 4; j++) {
            if (k0 + tx*4 + j >= TT) {
                #pragma unroll
                for (int i = 0; i < 4; i++) s[i][j] = -1e30f;
            }
        }

        #pragma unroll
        for (int i = 0; i < 4; i++) {
            float rm = fmaxf(fmaxf(s[i][0], s[i][1]), fmaxf(s[i][2], s[i][3]));
            rm = fmaxf(rm, __shfl_xor_sync(0xffffffffu, rm, 1));
            rm = fmaxf(rm, __shfl_xor_sync(0xffffffffu, rm, 2));
            rm = fmaxf(rm, __shfl_xor_sync(0xffffffffu, rm, 4));
            rm = fmaxf(rm, __shfl_xor_sync(0xffffffffu, rm, 8));
            float mn = fmaxf(m_i[i], rm);
            float alpha = __expf(m_i[i] - mn);
            float rs = 0.f;
            #pragma unroll
            for (int j = 0; j < 4; j++) { s[i][j] = __expf(s[i][j] - mn); rs += s[i][j]; }
            rs += __shfl_xor_sync(0xffffffffu, rs, 1);
            rs += __shfl_xor_sync(0xffffffffu, rs, 2);
            rs += __shfl_xor_sync(0xffffffffu, rs, 4);
            rs += __shfl_xor_sync(0xffffffffu, rs, 8);
            l_i[i] = l_i[i] * alpha + rs;
            m_i[i] = mn;
            unsigned long long al = dup2(alpha);
            o2[i][0] = mul2(o2[i][0], al);
            o2[i][1] = mul2(o2[i][1], al);
        }

        __syncthreads();
        #pragma unroll
        for (int i = 0; i < 4; i++)
            *(float4*)&KtPs[(ty*4 + i) * 64 + tx*4] = make_float4(s[i][0], s[i][1], s[i][2], s[i][3]);
        __syncthreads();

        #pragma unroll 2
        for (int kk = 0; kk < 64; kk++) {
            const unsigned long long* vp = (const unsigned long long*)(Vs + kk*64 + tx*4);
            unsigned long long v01 = vp[0], v23 = vp[1];
            #pragma unroll
            for (int i = 0; i < 4; i++) {
                unsigned long long pd = dup2(KtPs[(ty*4 + i)*64 + kk]);
                fma2(o2[i][0], pd, v01);
                fma2(o2[i][1], pd, v23);
            }
        }
    }

    #pragma unroll
    for (int i = 0; i < 4; i++) {
        int row = q0 + ty*4 + i;
        if (row >= TT) continue;
        float inv = 1.0f / l_i[i];
        float2 a = un2(o2[i][0]), b = un2(o2[i][1]);
        float* dst = g_ctx + ((size_t)(b_ * TT + row)) * EE + h_ * DH + tx * 4;
        *(float4*)dst = make_float4(a.x*inv, a.y*inv, b.x*inv, b.y*inv);
    }
}

extern "C" void kernel_launch(void* const* d_in, const int* in_sizes, int n_in,
                              void* d_out, int out_size)
{
    const float* X  = (const float*)d_in[0];
    const float* Wq = (const float*)d_in[1];
    const float* bq = (const float*)d_in[2];
    const float* Wk = (const float*)d_in[3];
    const float* Wv = (const float*)d_in[4];
    const float* bv = (const float*)d_in[5];
    const float* Wo = (const float*)d_in[6];
    const float* bo = (const float*)d_in[7];
    float* out = (float*)d_out;

    cudaFuncSetAttribute(qkv_mm, cudaFuncAttributeMaxDynamicSharedMemorySize, SMEM_TOTAL);
    cudaFuncSetAttribute(out_mm, cudaFuncAttributeMaxDynamicSharedMemorySize, SMEM_TOTAL);

    dim3 g1(30, 47);
    qkv_mm<<<g1, 256, SMEM_TOTAL>>>(X, Wq, bq, Wk, Wv, bv);

    dim3 g2(24, NB * NH);
    attn_kernel<<<g2, 256>>>();

    dim3 g3(10, 47);
    out_mm<<<g3, 256, SMEM_TOTAL>>>(Wo, bo, out);
}

// round 5
// speedup vs baseline: 2.3001x; 1.8728x over previous
#include <cuda_runtime.h>
#include <cuda_bf16.h>
#include <cstdint>

// Problem constants
#define NB 4
#define TT 1500
#define EE 1280
#define NH 20
#define DH 64
#define MR (NB*TT)          // 6000 rows
#define QKSCALE 0.125f

// GEMM tiling: block 128x128, k-chunk 16, 8 warps (2x4), warp tile 64x32
#define BK 16
#define NCH (EE/BK)         // 80 chunks
#define ROWSTRIDE 48        // bytes per smem row (16 bf16 + 8 pad)
#define TILE_SZ (128*ROWSTRIDE)      // 6144 B per bf16 tile
#define STAGE_SZ (4*TILE_SZ)         // Ahi,Alo,Bhi,Blo = 24576 B
#define SMEM_TOTAL (2*STAGE_SZ)      // 49152 B

// Attention smem: 6 tiles of 64x64 bf16, 144B row stride
#define ATS 144
#define ATILE (64*ATS)               // 9216 B
#define AQH 0
#define AQL (1*ATILE)
#define AKH (2*ATILE)
#define AKL (3*ATILE)
#define AVH (4*ATILE)
#define AVL (5*ATILE)
#define ASMEM (6*ATILE)              // 55296 B

// Scratch
static __device__ float g_q[(size_t)NB*NH*TT*DH];    // [b,h,t,d]
static __device__ float g_k[(size_t)NB*NH*TT*DH];
static __device__ float g_v[(size_t)NB*NH*TT*DH];
static __device__ float g_ctx[(size_t)MR*EE];        // [b*T+t, h*64+d]

// ---------------- tensor-core helpers (sm_80-compatible PTX) ----------------
__device__ __forceinline__ uint32_t smem_u32(const void* p){
    uint32_t a;
    asm("{ .reg .u64 t; cvta.to.shared.u64 t, %1; cvt.u32.u64 %0, t; }" : "=r"(a) : "l"(p));
    return a;
}
__device__ __forceinline__ void ldx4(uint32_t* r, uint32_t addr){
    asm volatile("ldmatrix.sync.aligned.m8n8.x4.shared.b16 {%0,%1,%2,%3}, [%4];"
        : "=r"(r[0]), "=r"(r[1]), "=r"(r[2]), "=r"(r[3]) : "r"(addr));
}
__device__ __forceinline__ void ldx2(uint32_t* r, uint32_t addr){
    asm volatile("ldmatrix.sync.aligned.m8n8.x2.shared.b16 {%0,%1}, [%2];"
        : "=r"(r[0]), "=r"(r[1]) : "r"(addr));
}
__device__ __forceinline__ void ldx2t(uint32_t* r, uint32_t addr){
    asm volatile("ldmatrix.sync.aligned.m8n8.x2.trans.shared.b16 {%0,%1}, [%2];"
        : "=r"(r[0]), "=r"(r[1]) : "r"(addr));
}
__device__ __forceinline__ void mma_bf16(float* d, const uint32_t* a, const uint32_t* b){
    asm volatile(
        "mma.sync.aligned.m16n8k16.row.col.f32.bf16.bf16.f32 "
        "{%0,%1,%2,%3}, {%4,%5,%6,%7}, {%8,%9}, {%0,%1,%2,%3};"
        : "+f"(d[0]), "+f"(d[1]), "+f"(d[2]), "+f"(d[3])
        : "r"(a[0]), "r"(a[1]), "r"(a[2]), "r"(a[3]), "r"(b[0]), "r"(b[1]));
}

// Split float4 into bf16 hi (rounded) and lo (residual) packed pairs.
__device__ __forceinline__ void split4(float4 f, uint2& H, uint2& L){
    __nv_bfloat16 hx = __float2bfloat16(f.x);
    __nv_bfloat16 hy = __float2bfloat16(f.y);
    __nv_bfloat16 hz = __float2bfloat16(f.z);
    __nv_bfloat16 hw = __float2bfloat16(f.w);
    float lx = f.x - __bfloat162float(hx);
    float ly = f.y - __bfloat162float(hy);
    float lz = f.z - __bfloat162float(hz);
    float lw = f.w - __bfloat162float(hw);
    union { __nv_bfloat162 h2[2]; uint2 u; } A, B;
    A.h2[0] = __halves2bfloat162(hx, hy);
    A.h2[1] = __halves2bfloat162(hz, hw);
    B.h2[0] = __floats2bfloat162_rn(lx, ly);
    B.h2[1] = __floats2bfloat162_rn(lz, lw);
    H = A.u; L = B.u;
}
// Split a pair of floats into packed bf16x2 hi and lo.
__device__ __forceinline__ void splitp(float a, float b, uint32_t& H, uint32_t& L){
    __nv_bfloat16 ha = __float2bfloat16(a);
    __nv_bfloat16 hb = __float2bfloat16(b);
    float la = a - __bfloat162float(ha);
    float lb = b - __bfloat162float(hb);
    union { __nv_bfloat162 h; uint32_t u; } X, Y;
    X.h = __halves2bfloat162(ha, hb);
    Y.h = __floats2bfloat162_rn(la, lb);
    H = X.u; L = Y.u;
}

// ============================================================================
// GEMM main loop (unchanged from R3): acc(128x128) += A @ B^T, bf16 split.
// ============================================================================
__device__ __forceinline__ void mm_loop(
    const float* __restrict__ Ab, const float* __restrict__ Bb, int row0,
    char* sm, uint32_t smb, float acc[4][4][4])
{
    const int tid  = threadIdx.x;
    const int lane = tid & 31;
    const int wid  = tid >> 5;
    const int warp_m = wid >> 2;
    const int warp_n = wid & 3;

    const int srow  = tid >> 1;
    const int shalf = (tid & 1) * 8;
    const bool aval = (row0 + srow) < MR;
    const float* ap = Ab + (size_t)(row0 + srow) * EE + shalf;
    const float* bp = Bb + (size_t)srow * EE + shalf;

    const uint32_t a_rd = smb + (uint32_t)(warp_m*64 + (lane & 15)) * ROWSTRIDE + (lane >> 4) * 16;
    const uint32_t b_rd = smb + 2*TILE_SZ + (uint32_t)(warp_n*32 + (lane & 7)) * ROWSTRIDE + ((lane >> 3) & 1) * 16;
    const uint32_t st0 = (uint32_t)srow * ROWSTRIDE + shalf * 2;

    float4 a0, a1, b0, b1;
    a0 = aval ? *(const float4*)(ap)     : make_float4(0.f,0.f,0.f,0.f);
    a1 = aval ? *(const float4*)(ap + 4) : make_float4(0.f,0.f,0.f,0.f);
    b0 = *(const float4*)(bp);
    b1 = *(const float4*)(bp + 4);

    #pragma unroll 1
    for (int i = 0; i < NCH; i++) {
        char* stg = sm + (i & 1) * STAGE_SZ;
        uint2 H, L;
        split4(a0, H, L);
        *(uint2*)(stg + st0)               = H;
        *(uint2*)(stg + TILE_SZ + st0)     = L;
        split4(a1, H, L);
        *(uint2*)(stg + st0 + 8)           = H;
        *(uint2*)(stg + TILE_SZ + st0 + 8) = L;
        split4(b0, H, L);
        *(uint2*)(stg + 2*TILE_SZ + st0)       = H;
        *(uint2*)(stg + 3*TILE_SZ + st0)       = L;
        split4(b1, H, L);
        *(uint2*)(stg + 2*TILE_SZ + st0 + 8)   = H;
        *(uint2*)(stg + 3*TILE_SZ + st0 + 8)   = L;

        if (i + 1 < NCH) {
            const float* apn = ap + (i+1)*BK;
            const float* bpn = bp + (i+1)*BK;
            a0 = aval ? *(const float4*)(apn)     : make_float4(0.f,0.f,0.f,0.f);
            a1 = aval ? *(const float4*)(apn + 4) : make_float4(0.f,0.f,0.f,0.f);
            b0 = *(const float4*)(bpn);
            b1 = *(const float4*)(bpn + 4);
        }
        __syncthreads();

        const uint32_t soff = (uint32_t)(i & 1) * STAGE_SZ;
        uint32_t bh[4][2], bl[4][2];
        #pragma unroll
        for (int nt = 0; nt < 4; nt++) {
            ldx2(bh[nt], b_rd + soff + nt*8*ROWSTRIDE);
            ldx2(bl[nt], b_rd + soff + nt*8*ROWSTRIDE + TILE_SZ);
        }
        #pragma unroll
        for (int mt = 0; mt < 4; mt++) {
            uint32_t ah[4], al[4];
            ldx4(ah, a_rd + soff + mt*16*ROWSTRIDE);
            ldx4(al, a_rd + soff + mt*16*ROWSTRIDE + TILE_SZ);
            #pragma unroll
            for (int nt = 0; nt < 4; nt++) {
                mma_bf16(acc[mt][nt], ah, bh[nt]);
                mma_bf16(acc[mt][nt], ah, bl[nt]);
                mma_bf16(acc[mt][nt], al, bh[nt]);
            }
        }
        __syncthreads();
    }
}

// ============================================================================
// QKV GEMM: grid (30, 47). blockIdx.x: 0-9 q, 10-19 k, 20-29 v.
// ============================================================================
__global__ __launch_bounds__(256, 2) void qkv_mm(
    const float* __restrict__ X,
    const float* __restrict__ Wq, const float* __restrict__ bq,
    const float* __restrict__ Wk,
    const float* __restrict__ Wv, const float* __restrict__ bv)
{
    extern __shared__ char sm[];
    uint32_t smb = smem_u32(sm);
    const int tid = threadIdx.x;
    const int lane = tid & 31;
    const int wid = tid >> 5;
    const int warp_m = wid >> 2, warp_n = wid & 3;

    const int which = blockIdx.x / 10;
    const int wcol0 = (blockIdx.x - which*10) * 128;
    const int row0  = blockIdx.y * 128;
    const float* W = (which == 0) ? Wq : (which == 1 ? Wk : Wv);
    const float* bias = (which == 0) ? bq : (which == 2 ? bv : nullptr);
    const float scl = (which == 0) ? QKSCALE : 1.0f;
    float* dstBase = (which == 0) ? g_q : (which == 1 ? g_k : g_v);

    float acc[4][4][4];
    #pragma unroll
    for (int mt = 0; mt < 4; mt++)
        #pragma unroll
        for (int nt = 0; nt < 4; nt++)
            #pragma unroll
            for (int j = 0; j < 4; j++) acc[mt][nt][j] = 0.f;

    mm_loop(X, W + (size_t)wcol0 * EE, row0, sm, smb, acc);

    const int g = lane >> 2, t4 = lane & 3;
    #pragma unroll
    for (int mt = 0; mt < 4; mt++) {
        #pragma unroll
        for (int nt = 0; nt < 4; nt++) {
            int col = wcol0 + warp_n*32 + nt*8 + 2*t4;
            float2 bb = bias ? *(const float2*)(bias + col) : make_float2(0.f, 0.f);
            int h = col >> 6, d = col & 63;
            int r0w = row0 + warp_m*64 + mt*16 + g;
            if (r0w < MR) {
                int b_ = r0w / TT, t_ = r0w - b_*TT;
                float2 v = make_float2((acc[mt][nt][0] + bb.x)*scl, (acc[mt][nt][1] + bb.y)*scl);
                *(float2*)(dstBase + ((size_t)(b_*NH + h)*TT + t_)*DH + d) = v;
            }
            int r1w = r0w + 8;
            if (r1w < MR) {
                int b_ = r1w / TT, t_ = r1w - b_*TT;
                float2 v = make_float2((acc[mt][nt][2] + bb.x)*scl, (acc[mt][nt][3] + bb.y)*scl);
                *(float2*)(dstBase + ((size_t)(b_*NH + h)*TT + t_)*DH + d) = v;
            }
        }
    }
}

// ============================================================================
// Output projection: out = ctx @ Wo^T + bo. grid (10, 47).
// ============================================================================
__global__ __launch_bounds__(256, 2) void out_mm(
    const float* __restrict__ Wo, const float* __restrict__ bo,
    float* __restrict__ out)
{
    extern __shared__ char sm[];
    uint32_t smb = smem_u32(sm);
    const int tid = threadIdx.x;
    const int lane = tid & 31;
    const int wid = tid >> 5;
    const int warp_m = wid >> 2, warp_n = wid & 3;
    const int col0 = blockIdx.x * 128;
    const int row0 = blockIdx.y * 128;

    float acc[4][4][4];
    #pragma unroll
    for (int mt = 0; mt < 4; mt++)
        #pragma unroll
        for (int nt = 0; nt < 4; nt++)
            #pragma unroll
            for (int j = 0; j < 4; j++) acc[mt][nt][j] = 0.f;

    mm_loop(g_ctx, Wo + (size_t)col0 * EE, row0, sm, smb, acc);

    const int g = lane >> 2, t4 = lane & 3;
    #pragma unroll
    for (int mt = 0; mt < 4; mt++) {
        #pragma unroll
        for (int nt = 0; nt < 4; nt++) {
            int col = col0 + warp_n*32 + nt*8 + 2*t4;
            float2 bb = *(const float2*)(bo + col);
            int r0w = row0 + warp_m*64 + mt*16 + g;
            if (r0w < MR) {
                float2 v = make_float2(acc[mt][nt][0] + bb.x, acc[mt][nt][1] + bb.y);
                *(float2*)(out + (size_t)r0w*EE + col) = v;
            }
            int r1w = r0w + 8;
            if (r1w < MR) {
                float2 v = make_float2(acc[mt][nt][2] + bb.x, acc[mt][nt][3] + bb.y);
                *(float2*)(out + (size_t)r1w*EE + col) = v;
            }
        }
    }
}

// ============================================================================
// Flash attention on tensor cores, bf16 3-term split everywhere.
// Grid (24 q-tiles, 80 heads), 128 threads (4 warps, 16 q-rows each).
// P stays in registers (S accumulator fragment == A operand fragment layout);
// V is trans-ldmatrix'd from natural [key][d] layout.
// ============================================================================
__global__ __launch_bounds__(128) void attn_kernel()
{
    extern __shared__ char sm[];
    uint32_t smb = smem_u32(sm);

    const int tid = threadIdx.x;
    const int lane = tid & 31;
    const int wid = tid >> 5;          // 0..3
    const int g  = lane >> 2;          // 0..7  (fragment row)
    const int t4 = lane & 3;           // 0..3  (fragment col pair)

    const int bh = blockIdx.y;
    const int b_ = bh / NH;
    const int h_ = bh - b_ * NH;
    const float* qb = g_q + (size_t)bh * TT * DH;
    const float* kb = g_k + (size_t)bh * TT * DH;
    const float* vb = g_v + (size_t)bh * TT * DH;
    const int q0 = blockIdx.x * 64;

    // ---- load Q tile (split into hi/lo bf16, 144B stride) ----
    const int srow = tid >> 1;             // 0..63
    const int c0   = (tid & 1) * 32;       // 0 or 32
    {
        int gr = q0 + srow;
        const float* qp = qb + (size_t)gr * DH + c0;
        #pragma unroll
        for (int j = 0; j < 8; j++) {
            float4 f = (gr < TT) ? *(const float4*)(qp + 4*j) : make_float4(0.f,0.f,0.f,0.f);
            uint2 H, L;
            split4(f, H, L);
            uint32_t off = (uint32_t)srow * ATS + (c0 + 4*j) * 2;
            *(uint2*)(sm + AQH + off) = H;
            *(uint2*)(sm + AQL + off) = L;
        }
    }
    __syncthreads();

    // ---- preload Q fragments (loop-invariant): 4 k-chunks x (hi,lo) ----
    uint32_t qh[4][4], ql[4][4];
    {
        uint32_t qa = smb + (uint32_t)(wid*16 + (lane & 15)) * ATS + (lane >> 4) * 16;
        #pragma unroll
        for (int kc = 0; kc < 4; kc++) {
            ldx4(qh[kc], qa + AQH + kc*32);
            ldx4(ql[kc], qa + AQL + kc*32);
        }
    }

    // ---- softmax state + output accumulators ----
    float m0 = -1e30f, m1 = -1e30f, l0 = 0.f, l1 = 0.f;
    float o[8][4];
    #pragma unroll
    for (int nt = 0; nt < 8; nt++)
        #pragma unroll
        for (int j = 0; j < 4; j++) o[nt][j] = 0.f;

    const uint32_t k_rd = smb + (uint32_t)(lane & 7) * ATS + ((lane >> 3) & 1) * 16;
    const uint32_t v_rd = smb + (uint32_t)(lane & 15) * ATS;

    #pragma unroll 1
    for (int kt = 0; kt < 24; kt++) {
        const int k0 = kt * 64;
        __syncthreads();   // everyone done reading previous K/V

        // ---- load K and V tiles (split) ----
        {
            int gr = k0 + srow;
            bool valid = gr < TT;
            const float* kp = kb + (size_t)gr * DH + c0;
            const float* vp = vb + (size_t)gr * DH + c0;
            uint32_t off = (uint32_t)srow * ATS + c0 * 2;
            #pragma unroll
            for (int j = 0; j < 8; j++) {
                float4 f = valid ? *(const float4*)(kp + 4*j) : make_float4(0.f,0.f,0.f,0.f);
                uint2 H, L;
                split4(f, H, L);
                *(uint2*)(sm + AKH + off + 8*j) = H;
                *(uint2*)(sm + AKL + off + 8*j) = L;
                float4 v = valid ? *(const float4*)(vp + 4*j) : make_float4(0.f,0.f,0.f,0.f);
                split4(v, H, L);
                *(uint2*)(sm + AVH + off + 8*j) = H;
                *(uint2*)(sm + AVL + off + 8*j) = L;
            }
        }
        __syncthreads();

        // ---- S = Q K^T (3-term split) ----
        float s[8][4];
        #pragma unroll
        for (int nt = 0; nt < 8; nt++)
            #pragma unroll
            for (int j = 0; j < 4; j++) s[nt][j] = 0.f;

        #pragma unroll
        for (int nt = 0; nt < 8; nt++) {
            uint32_t kbase = k_rd + (uint32_t)nt*8*ATS;
            #pragma unroll
            for (int kc = 0; kc < 4; kc++) {
                uint32_t kh[2], kl[2];
                ldx2(kh, kbase + AKH + kc*32);
                ldx2(kl, kbase + AKL + kc*32);
                mma_bf16(s[nt], qh[kc], kh);
                mma_bf16(s[nt], qh[kc], kl);
                mma_bf16(s[nt], ql[kc], kh);
            }
        }

        // ---- mask invalid key columns (last tile) ----
        if (k0 + 64 > TT) {
            #pragma unroll
            for (int nt = 0; nt < 8; nt++) {
                int col = k0 + nt*8 + 2*t4;
                if (col   >= TT) { s[nt][0] = -1e30f; s[nt][2] = -1e30f; }
                if (col+1 >= TT) { s[nt][1] = -1e30f; s[nt][3] = -1e30f; }
            }
        }

        // ---- online softmax (rows g and g+8) ----
        float mx0 = -1e30f, mx1 = -1e30f;
        #pragma unroll
        for (int nt = 0; nt < 8; nt++) {
            mx0 = fmaxf(mx0, fmaxf(s[nt][0], s[nt][1]));
            mx1 = fmaxf(mx1, fmaxf(s[nt][2], s[nt][3]));
        }
        mx0 = fmaxf(mx0, __shfl_xor_sync(0xffffffffu, mx0, 1));
        mx0 = fmaxf(mx0, __shfl_xor_sync(0xffffffffu, mx0, 2));
        mx1 = fmaxf(mx1, __shfl_xor_sync(0xffffffffu, mx1, 1));
        mx1 = fmaxf(mx1, __shfl_xor_sync(0xffffffffu, mx1, 2));

        float mn0 = fmaxf(m0, mx0), mn1 = fmaxf(m1, mx1);
        float al0 = __expf(m0 - mn0), al1 = __expf(m1 - mn1);
        m0 = mn0; m1 = mn1;

        float sum0 = 0.f, sum1 = 0.f;
        #pragma unroll
        for (int nt = 0; nt < 8; nt++) {
            s[nt][0] = __expf(s[nt][0] - mn0); sum0 += s[nt][0];
            s[nt][1] = __expf(s[nt][1] - mn0); sum0 += s[nt][1];
            s[nt][2] = __expf(s[nt][2] - mn1); sum1 += s[nt][2];
            s[nt][3] = __expf(s[nt][3] - mn1); sum1 += s[nt][3];
        }
        sum0 += __shfl_xor_sync(0xffffffffu, sum0, 1);
        sum0 += __shfl_xor_sync(0xffffffffu, sum0, 2);
        sum1 += __shfl_xor_sync(0xffffffffu, sum1, 1);
        sum1 += __shfl_xor_sync(0xffffffffu, sum1, 2);
        l0 = l0 * al0 + sum0;
        l1 = l1 * al1 + sum1;

        #pragma unroll
        for (int nt = 0; nt < 8; nt++) {
            o[nt][0] *= al0; o[nt][1] *= al0;
            o[nt][2] *= al1; o[nt][3] *= al1;
        }

        // ---- O += P V  (P in registers; V via trans-ldmatrix) ----
        #pragma unroll
        for (int kc = 0; kc < 4; kc++) {
            uint32_t ah[4], al_[4];
            splitp(s[2*kc][0],   s[2*kc][1],   ah[0], al_[0]);
            splitp(s[2*kc][2],   s[2*kc][3],   ah[1], al_[1]);
            splitp(s[2*kc+1][0], s[2*kc+1][1], ah[2], al_[2]);
            splitp(s[2*kc+1][2], s[2*kc+1][3], ah[3], al_[3]);
            uint32_t vbase = v_rd + (uint32_t)kc*16*ATS;
            #pragma unroll
            for (int nt = 0; nt < 8; nt++) {
                uint32_t vh[2], vl[2];
                ldx2t(vh, vbase + AVH + nt*16);
                ldx2t(vl, vbase + AVL + nt*16);
                mma_bf16(o[nt], ah,  vh);
                mma_bf16(o[nt], ah,  vl);
                mma_bf16(o[nt], al_, vh);
            }
        }
    }

    // ---- epilogue: normalize, write ctx [b*T+t, h*64+d] ----
    float inv0 = 1.0f / l0, inv1 = 1.0f / l1;
    int r0w = q0 + wid*16 + g;
    int r1w = r0w + 8;
    #pragma unroll
    for (int nt = 0; nt < 8; nt++) {
        int d = nt*8 + 2*t4;
        if (r0w < TT) {
            float* dst = g_ctx + ((size_t)(b_ * TT + r0w)) * EE + h_ * DH + d;
            *(float2*)dst = make_float2(o[nt][0]*inv0, o[nt][1]*inv0);
        }
        if (r1w < TT) {
            float* dst = g_ctx + ((size_t)(b_ * TT + r1w)) * EE + h_ * DH + d;
            *(float2*)dst = make_float2(o[nt][2]*inv1, o[nt][3]*inv1);
        }
    }
}

extern "C" void kernel_launch(void* const* d_in, const int* in_sizes, int n_in,
                              void* d_out, int out_size)
{
    const float* X  = (const float*)d_in[0];
    const float* Wq = (const float*)d_in[1];
    const float* bq = (const float*)d_in[2];
    const float* Wk = (const float*)d_in[3];
    const float* Wv = (const float*)d_in[4];
    const float* bv = (const float*)d_in[5];
    const float* Wo = (const float*)d_in[6];
    const float* bo = (const float*)d_in[7];
    float* out = (float*)d_out;

    cudaFuncSetAttribute(qkv_mm, cudaFuncAttributeMaxDynamicSharedMemorySize, SMEM_TOTAL);
    cudaFuncSetAttribute(out_mm, cudaFuncAttributeMaxDynamicSharedMemorySize, SMEM_TOTAL);
    cudaFuncSetAttribute(attn_kernel, cudaFuncAttributeMaxDynamicSharedMemorySize, ASMEM);

    dim3 g1(30, 47);
    qkv_mm<<<g1, 256, SMEM_TOTAL>>>(X, Wq, bq, Wk, Wv, bv);

    dim3 g2(24, NB * NH);
    attn_kernel<<<g2, 128, ASMEM>>>();

    dim3 g3(10, 47);
    out_mm<<<g3, 256, SMEM_TOTAL>>>(Wo, bo, out);
}